// round 1
// baseline (speedup 1.0000x reference)
#include <cuda_runtime.h>
#include <cstdint>

#define NQ    32
#define KCB   1024
#define CDIM  8
#define DDIM  1024
#define BDIMS 8
#define TDIM  4096
#define TILE  32
#define NTH   256
#define NCOLS (BDIMS*TDIM)          /* 32768 */
#define BDT   (BDIMS*DDIM*TDIM)    /* 33554432 */
#define NQBT  (NQ*NCOLS)           /* 1048576 */

// shared memory offsets (in floats)
#define SM_R   0                    /* 1024 x 32 residual, swizzled      */
#define SM_W   32768                /* 1024 x 12: iw^T (+pad) or ow|ob   */
#define SM_CB  (SM_W + 12288)       /* 1024 x 8 codebook                 */
#define SM_C2  (SM_CB + 8192)       /* 1024 |cb|^2                       */
#define SM_ZE  (SM_C2 + 1024)       /* 32 x 12 z_e                       */
#define SM_ZQ  (SM_ZE + 384)        /* 32 x 12 selected codeword * mask  */
#define SM_M   (SM_ZQ + 384)        /* 32 mask                           */
#define SM_BD  (SM_M + 32)          /* 8 x 32 partial argmin dist        */
#define SM_IB  (SM_BD + 256)        /* 8 bias                            */
#define SM_BK  (SM_IB + 8)          /* 8 x 32 partial argmin index (int) */
#define SM_TOTAL_FLOATS (SM_BK + 256)
#define SM_BYTES (SM_TOTAL_FLOATS * 4)

__global__ __launch_bounds__(NTH, 1)
void rvq_kernel(const float* __restrict__ z,
                const float* __restrict__ iw,
                const float* __restrict__ ibias,
                const float* __restrict__ ow,
                const float* __restrict__ obias,
                const float* __restrict__ cb,
                const int*   __restrict__ inlen,
                float* __restrict__ out,
                int wout, int widx, int wlen)
{
    extern __shared__ float sm[];
    float* r_s  = sm + SM_R;
    float* w_s  = sm + SM_W;
    float* cb_s = sm + SM_CB;
    float* c2_s = sm + SM_C2;
    float* ze_s = sm + SM_ZE;
    float* zq_s = sm + SM_ZQ;
    float* m_s  = sm + SM_M;
    float* bd_s = sm + SM_BD;
    float* ib_s = sm + SM_IB;
    int*   bk_s = (int*)(sm + SM_BK);
    float4* R4  = (float4*)r_s;

    const int tid  = threadIdx.x;
    const int lane = tid & 31;
    const int w    = tid >> 5;          // warp id 0..7
    const int col0 = blockIdx.x * TILE; // global column base
    const int b    = col0 >> 12;        // col0 / TDIM
    const int t0   = col0 & (TDIM - 1);
    const int len  = inlen[b];

    const float* zb = z + (size_t)b * DDIM * TDIM + t0;

    // ---- init: mask + residual = z * mask (masked cols start at 0) ----
    if (tid < TILE) m_s[tid] = ((t0 + tid) < len) ? 1.0f : 0.0f;
    for (int i = tid; i < DDIM * 8; i += NTH) {
        int d = i >> 3, tq = i & 7;
        float4 v = *(const float4*)(zb + (size_t)d * TDIM + (tq << 2));
        int tb = t0 + (tq << 2);
        v.x = (tb + 0 < len) ? v.x : 0.0f;
        v.y = (tb + 1 < len) ? v.y : 0.0f;
        v.z = (tb + 2 < len) ? v.z : 0.0f;
        v.w = (tb + 3 < len) ? v.w : 0.0f;
        R4[d * 8 + (tq ^ (d & 7))] = v;
    }
    __syncthreads();

    for (int q = 0; q < NQ; q++) {
        // ---- stage A: iw^T -> w_s, codebook -> cb_s, |cb|^2, bias ----
        const float* iwq = iw + q * (CDIM * DDIM);
        for (int i = tid; i < CDIM * DDIM; i += NTH) {
            int c = i >> 10, d = i & 1023;
            w_s[d * 12 + c] = iwq[i];
        }
        const float* cbq = cb + q * (KCB * CDIM);
        for (int i = tid; i < (KCB * CDIM) / 4; i += NTH)
            ((float4*)cb_s)[i] = ((const float4*)cbq)[i];
        for (int k = tid; k < KCB; k += NTH) {
            const float* row = cbq + k * 8;
            float s = 0.f;
            #pragma unroll
            for (int c = 0; c < 8; c++) s = fmaf(row[c], row[c], s);
            c2_s[k] = s;
        }
        if (tid < CDIM) ib_s[tid] = ibias[q * CDIM + tid];
        __syncthreads();

        // ---- phase 1: z_e[c][t] = sum_d iw[c][d] * r[d][t] ----
        {
            float acc[8][4];
            #pragma unroll
            for (int c = 0; c < 8; c++)
                #pragma unroll
                for (int j = 0; j < 4; j++) acc[c][j] = 0.f;

            #pragma unroll 4
            for (int i = 0; i < 32; i++) {
                int d = lane + (i << 5);
                float4 r4 = R4[d * 8 + (w ^ (d & 7))];
                float4 wa = *(const float4*)(w_s + d * 12);
                float4 wb = *(const float4*)(w_s + d * 12 + 4);
                float wc[8] = {wa.x, wa.y, wa.z, wa.w, wb.x, wb.y, wb.z, wb.w};
                #pragma unroll
                for (int c = 0; c < 8; c++) {
                    acc[c][0] = fmaf(wc[c], r4.x, acc[c][0]);
                    acc[c][1] = fmaf(wc[c], r4.y, acc[c][1]);
                    acc[c][2] = fmaf(wc[c], r4.z, acc[c][2]);
                    acc[c][3] = fmaf(wc[c], r4.w, acc[c][3]);
                }
            }
            #pragma unroll
            for (int off = 16; off > 0; off >>= 1)
                #pragma unroll
                for (int c = 0; c < 8; c++)
                    #pragma unroll
                    for (int j = 0; j < 4; j++)
                        acc[c][j] += __shfl_xor_sync(0xffffffffu, acc[c][j], off);
            if (lane == 0) {
                int tb = w << 2;
                #pragma unroll
                for (int j = 0; j < 4; j++)
                    #pragma unroll
                    for (int c = 0; c < 8; c++)
                        ze_s[(tb + j) * 12 + c] = acc[c][j] + ib_s[c];
            }
        }
        __syncthreads();

        // ---- stage B (overlaps phase 2): ow|ob -> w_s ----
        const float* owq = ow + q * (DDIM * CDIM);
        for (int i = tid; i < DDIM * 2; i += NTH) {
            int d = i >> 1, h = i & 1;
            *(float4*)(w_s + d * 12 + h * 4) = ((const float4*)owq)[i];
        }
        const float* obq = obias + q * DDIM;
        for (int d = tid; d < DDIM; d += NTH) w_s[d * 12 + 8] = obq[d];

        // ---- phase 2: distances + per-chunk argmin ----
        {
            int t = lane;            // warp handles one k-chunk, lanes = columns
            float4 eA = *(const float4*)(ze_s + t * 12);
            float4 eB = *(const float4*)(ze_s + t * 12 + 4);
            float e2 = 0.f;
            e2 = fmaf(eA.x, eA.x, e2); e2 = fmaf(eA.y, eA.y, e2);
            e2 = fmaf(eA.z, eA.z, e2); e2 = fmaf(eA.w, eA.w, e2);
            e2 = fmaf(eB.x, eB.x, e2); e2 = fmaf(eB.y, eB.y, e2);
            e2 = fmaf(eB.z, eB.z, e2); e2 = fmaf(eB.w, eB.w, e2);

            float best = 3.402823466e38f;
            int bk = 0;
            #pragma unroll 4
            for (int i = 0; i < 128; i++) {
                int k = (w << 7) + i;   // ascending -> first-min tie break
                float4 cA = ((const float4*)cb_s)[k * 2];
                float4 cB = ((const float4*)cb_s)[k * 2 + 1];
                float s = 0.f;
                s = fmaf(cA.x, eA.x, s); s = fmaf(cA.y, eA.y, s);
                s = fmaf(cA.z, eA.z, s); s = fmaf(cA.w, eA.w, s);
                s = fmaf(cB.x, eB.x, s); s = fmaf(cB.y, eB.y, s);
                s = fmaf(cB.z, eB.z, s); s = fmaf(cB.w, eB.w, s);
                float dist = (e2 - 2.0f * s) + c2_s[k];
                if (dist < best) { best = dist; bk = k; }
            }
            bd_s[(w << 5) + t] = best;
            bk_s[(w << 5) + t] = bk;
        }
        __syncthreads();

        // ---- final argmin across chunks + stage zq * mask ----
        if (tid < TILE) {
            int t = tid;
            float best = bd_s[t];
            int bk = bk_s[t];
            #pragma unroll
            for (int kc = 1; kc < 8; kc++) {     // ascending kc -> lowest index wins
                float d2 = bd_s[(kc << 5) + t];
                if (d2 < best) { best = d2; bk = bk_s[(kc << 5) + t]; }
            }
            if (widx) out[BDT + q * NCOLS + col0 + t] = (float)bk;
            float m = m_s[t];
            const float* row = cb_s + bk * 8;
            #pragma unroll
            for (int c = 0; c < 8; c++) zq_s[t * 12 + c] = row[c] * m;
        }
        __syncthreads();

        // ---- phase 3: r[d][t] -= (sum_c ow[d][c]*zq[c][t] + ob[d])*m[t] ----
        {
            int tb = w << 2;
            float zq[8][4], mj[4];
            #pragma unroll
            for (int j = 0; j < 4; j++) {
                mj[j] = m_s[tb + j];
                #pragma unroll
                for (int c = 0; c < 8; c++) zq[c][j] = zq_s[(tb + j) * 12 + c];
            }
            #pragma unroll 4
            for (int i = 0; i < 32; i++) {
                int d = lane + (i << 5);
                float4 wa = *(const float4*)(w_s + d * 12);
                float4 wb = *(const float4*)(w_s + d * 12 + 4);
                float obv = w_s[d * 12 + 8];
                float wc[8] = {wa.x, wa.y, wa.z, wa.w, wb.x, wb.y, wb.z, wb.w};
                int slot = d * 8 + (w ^ (d & 7));
                float4 r4 = R4[slot];
                float u0 = obv * mj[0], u1 = obv * mj[1];
                float u2 = obv * mj[2], u3 = obv * mj[3];
                #pragma unroll
                for (int c = 0; c < 8; c++) {
                    u0 = fmaf(wc[c], zq[c][0], u0);
                    u1 = fmaf(wc[c], zq[c][1], u1);
                    u2 = fmaf(wc[c], zq[c][2], u2);
                    u3 = fmaf(wc[c], zq[c][3], u3);
                }
                r4.x -= u0; r4.y -= u1; r4.z -= u2; r4.w -= u3;
                R4[slot] = r4;
            }
        }
        __syncthreads();
    }

    // ---- epilogue: qout = z*mask - r_final ----
    if (wout) {
        for (int i = tid; i < DDIM * 8; i += NTH) {
            int d = i >> 3, tq = i & 7;
            float4 zv = *(const float4*)(zb + (size_t)d * TDIM + (tq << 2));
            float4 rv = R4[d * 8 + (tq ^ (d & 7))];
            int tb = t0 + (tq << 2);
            float4 o;
            o.x = ((tb + 0 < len) ? zv.x : 0.0f) - rv.x;
            o.y = ((tb + 1 < len) ? zv.y : 0.0f) - rv.y;
            o.z = ((tb + 2 < len) ? zv.z : 0.0f) - rv.z;
            o.w = ((tb + 3 < len) ? zv.w : 0.0f) - rv.w;
            *(float4*)(out + (size_t)b * DDIM * TDIM + (size_t)d * TDIM + t0 + (tq << 2)) = o;
        }
    }
    if (wlen && blockIdx.x == 0 && tid < BDIMS)
        out[BDT + NQBT + tid] = (float)inlen[tid];
}

extern "C" void kernel_launch(void* const* d_in, const int* in_sizes, int n_in,
                              void* d_out, int out_size)
{
    const float* z   = (const float*)d_in[0];
    const float* iw  = (const float*)d_in[1];
    const float* ib  = (const float*)d_in[2];
    const float* ow  = (const float*)d_in[3];
    const float* ob  = (const float*)d_in[4];
    const float* cbk = (const float*)d_in[5];
    const int* inlen = (const int*)d_in[6];
    float* out = (float*)d_out;

    cudaFuncSetAttribute(rvq_kernel, cudaFuncAttributeMaxDynamicSharedMemorySize, SM_BYTES);

    int wout = (out_size >= BDT) ? 1 : 0;
    int widx = (out_size >= BDT + NQBT) ? 1 : 0;
    int wlen = (out_size >= BDT + NQBT + BDIMS) ? 1 : 0;

    rvq_kernel<<<NCOLS / TILE, NTH, SM_BYTES>>>(z, iw, ib, ow, ob, cbk, inlen,
                                               out, wout, widx, wlen);
}